// round 1
// baseline (speedup 1.0000x reference)
#include <cuda_runtime.h>
#include <math.h>

#define IMG_H 200
#define IMG_W 200
#define IMG_C 256
#define C4 (IMG_C / 4)   // 64 float4 per pixel

// One CTA per (roi, py, px) cell. 64 threads, each handles 4 channels (float4).
__global__ void roipool_kernel(const float* __restrict__ img,
                               const float* __restrict__ rois,
                               float* __restrict__ out,
                               int n_rois, int ps) {
    const int bid  = blockIdx.x;
    const int pp   = ps * ps;
    const int r    = bid / pp;
    const int cell = bid - r * pp;
    const int py   = cell / ps;
    const int px   = cell - py * ps;
    if (r >= n_rois) return;

    // RoI: [x, y, w, h] as float -> int (matches rois.astype(int32))
    const float4 rv = reinterpret_cast<const float4*>(rois)[r];
    const int x = (int)rv.x;
    const int y = (int)rv.y;
    const int w = (int)rv.z;
    const int h = (int)rv.w;

    const float sy = (float)h / (float)ps;
    const float sx = (float)w / (float)ps;
    const float src_y = (float)py * sy;
    const float src_x = (float)px * sx;
    const int y0 = (int)floorf(src_y);
    const int x0 = (int)floorf(src_x);
    const float wy = src_y - (float)y0;
    const float wx = src_x - (float)x0;

    const int gy0 = min(max(y + min(max(y0,     0), h - 1), 0), IMG_H - 1);
    const int gy1 = min(max(y + min(max(y0 + 1, 0), h - 1), 0), IMG_H - 1);
    const int gx0 = min(max(x + min(max(x0,     0), w - 1), 0), IMG_W - 1);
    const int gx1 = min(max(x + min(max(x0 + 1, 0), w - 1), 0), IMG_W - 1);

    const float4* __restrict__ f4 = reinterpret_cast<const float4*>(img);
    const int c = threadIdx.x;  // 0..C4-1

    const float4 v00 = f4[(gy0 * IMG_W + gx0) * C4 + c];
    const float4 v01 = f4[(gy0 * IMG_W + gx1) * C4 + c];
    const float4 v10 = f4[(gy1 * IMG_W + gx0) * C4 + c];
    const float4 v11 = f4[(gy1 * IMG_W + gx1) * C4 + c];

    const float omwx = 1.0f - wx;
    const float omwy = 1.0f - wy;

    float4 res;
    {
        float top = v00.x * omwx + v01.x * wx;
        float bot = v10.x * omwx + v11.x * wx;
        res.x = top * omwy + bot * wy;
    }
    {
        float top = v00.y * omwx + v01.y * wx;
        float bot = v10.y * omwx + v11.y * wx;
        res.y = top * omwy + bot * wy;
    }
    {
        float top = v00.z * omwx + v01.z * wx;
        float bot = v10.z * omwx + v11.z * wx;
        res.z = top * omwy + bot * wy;
    }
    {
        float top = v00.w * omwx + v01.w * wx;
        float bot = v10.w * omwx + v11.w * wx;
        res.w = top * omwy + bot * wy;
    }

    reinterpret_cast<float4*>(out)[(size_t)bid * C4 + c] = res;
}

extern "C" void kernel_launch(void* const* d_in, const int* in_sizes, int n_in,
                              void* d_out, int out_size) {
    const float* img  = (const float*)d_in[0];
    const float* rois = (const float*)d_in[1];
    float* out = (float*)d_out;

    const int n_rois = in_sizes[1] / 4;
    // out_size = n_rois * ps*ps * C  ->  ps = sqrt(out_size / (n_rois * C))
    const int pp = out_size / (n_rois * IMG_C);
    int ps = (int)(sqrtf((float)pp) + 0.5f);
    if (ps < 1) ps = 1;

    const int blocks = n_rois * ps * ps;
    roipool_kernel<<<blocks, C4>>>(img, rois, out, n_rois, ps);
}

// round 2
// speedup vs baseline: 1.6527x; 1.6527x over previous
#include <cuda_runtime.h>
#include <math.h>

#define IMG_H 200
#define IMG_W 200
#define IMG_C 256
#define C4 (IMG_C / 4)   // 64 float4 per pixel

// One CTA per RoI. 256 threads = 8 warps. Each warp processes one pooled cell
// at a time (looping over ps*ps cells); each lane handles channels
// {lane, lane+32} as float4 -> 8 independent global loads in flight per thread.
__global__ __launch_bounds__(256) void roipool_kernel(
        const float* __restrict__ img,
        const float* __restrict__ rois,
        float* __restrict__ out,
        int ps) {
    const int r     = blockIdx.x;
    const int warp  = threadIdx.x >> 5;
    const int lane  = threadIdx.x & 31;
    const int nwarp = blockDim.x >> 5;
    const int pp    = ps * ps;

    // RoI: [x, y, w, h] float -> int (matches rois.astype(int32))
    const float4 rv = reinterpret_cast<const float4*>(rois)[r];
    const int x = (int)rv.x;
    const int y = (int)rv.y;
    const int w = (int)rv.z;
    const int h = (int)rv.w;

    const float sy = (float)h / (float)ps;
    const float sx = (float)w / (float)ps;

    const float4* __restrict__ f4 = reinterpret_cast<const float4*>(img);
    float4* __restrict__ o4 = reinterpret_cast<float4*>(out) + (size_t)r * pp * C4;

    for (int cell = warp; cell < pp; cell += nwarp) {
        const int py = cell / ps;
        const int px = cell - py * ps;

        const float src_y = (float)py * sy;
        const float src_x = (float)px * sx;
        const int y0 = (int)floorf(src_y);
        const int x0 = (int)floorf(src_x);
        const float wy = src_y - (float)y0;
        const float wx = src_x - (float)x0;

        const int gy0 = min(max(y + min(max(y0,     0), h - 1), 0), IMG_H - 1);
        const int gy1 = min(max(y + min(max(y0 + 1, 0), h - 1), 0), IMG_H - 1);
        const int gx0 = min(max(x + min(max(x0,     0), w - 1), 0), IMG_W - 1);
        const int gx1 = min(max(x + min(max(x0 + 1, 0), w - 1), 0), IMG_W - 1);

        const float4* __restrict__ p00 = f4 + (size_t)(gy0 * IMG_W + gx0) * C4;
        const float4* __restrict__ p01 = f4 + (size_t)(gy0 * IMG_W + gx1) * C4;
        const float4* __restrict__ p10 = f4 + (size_t)(gy1 * IMG_W + gx0) * C4;
        const float4* __restrict__ p11 = f4 + (size_t)(gy1 * IMG_W + gx1) * C4;

        const int ca = lane;
        const int cb = lane + 32;

        // 8 independent loads -> deep MLP
        const float4 a00 = p00[ca];
        const float4 a01 = p01[ca];
        const float4 a10 = p10[ca];
        const float4 a11 = p11[ca];
        const float4 b00 = p00[cb];
        const float4 b01 = p01[cb];
        const float4 b10 = p10[cb];
        const float4 b11 = p11[cb];

        const float omwx = 1.0f - wx;
        const float omwy = 1.0f - wy;

        float4 ra, rb;
        {
            float t, b;
            t = a00.x * omwx + a01.x * wx; b = a10.x * omwx + a11.x * wx; ra.x = t * omwy + b * wy;
            t = a00.y * omwx + a01.y * wx; b = a10.y * omwx + a11.y * wx; ra.y = t * omwy + b * wy;
            t = a00.z * omwx + a01.z * wx; b = a10.z * omwx + a11.z * wx; ra.z = t * omwy + b * wy;
            t = a00.w * omwx + a01.w * wx; b = a10.w * omwx + a11.w * wx; ra.w = t * omwy + b * wy;

            t = b00.x * omwx + b01.x * wx; b = b10.x * omwx + b11.x * wx; rb.x = t * omwy + b * wy;
            t = b00.y * omwx + b01.y * wx; b = b10.y * omwx + b11.y * wx; rb.y = t * omwy + b * wy;
            t = b00.z * omwx + b01.z * wx; b = b10.z * omwx + b11.z * wx; rb.z = t * omwy + b * wy;
            t = b00.w * omwx + b01.w * wx; b = b10.w * omwx + b11.w * wx; rb.w = t * omwy + b * wy;
        }

        float4* __restrict__ oc = o4 + (size_t)cell * C4;
        oc[ca] = ra;
        oc[cb] = rb;
    }
}

extern "C" void kernel_launch(void* const* d_in, const int* in_sizes, int n_in,
                              void* d_out, int out_size) {
    const float* img  = (const float*)d_in[0];
    const float* rois = (const float*)d_in[1];
    float* out = (float*)d_out;

    const int n_rois = in_sizes[1] / 4;
    const int pp = out_size / (n_rois * IMG_C);
    int ps = (int)(sqrtf((float)pp) + 0.5f);
    if (ps < 1) ps = 1;

    roipool_kernel<<<n_rois, 256>>>(img, rois, out, ps);
}